// round 1
// baseline (speedup 1.0000x reference)
#include <cuda_runtime.h>

#define NN 50000
#define EE 800000
#define F 64
#define GG 64
#define CC 10

// ---------------- scratch (device globals; no allocation allowed) ----------------
__device__ __align__(16) float g_wdeg[NN];
__device__ __align__(16) float g_dinv[NN];
__device__ __align__(16) int   g_degcnt[NN];
__device__ __align__(16) int   g_rowptr[NN + 1];
__device__ __align__(16) int   g_fill[NN];
__device__ __align__(16) int2  g_edges[EE];      // (col, bitcast(norm)) sorted by row
__device__ __align__(16) float g_T1[NN * F];
__device__ __align__(16) float g_T2[NN * F];
__device__ __align__(16) float g_H0[NN * F];
__device__ __align__(16) float g_H1[NN * F];
__device__ __align__(16) float g_pool[GG * F];

// ---------------- build: degree, dinv, CSR ----------------
__global__ void zero_kernel() {
    int i = blockIdx.x * blockDim.x + threadIdx.x;
    if (i < NN) { g_wdeg[i] = 0.f; g_degcnt[i] = 0; }
}

__global__ void deg_kernel(const int* __restrict__ ei, const float* __restrict__ attr) {
    int e = blockIdx.x * blockDim.x + threadIdx.x;
    if (e < EE) {
        int r = ei[e];
        atomicAdd(&g_wdeg[r], attr[e]);
        atomicAdd(&g_degcnt[r], 1);
    }
}

__global__ void dinv_kernel() {
    int i = blockIdx.x * blockDim.x + threadIdx.x;
    if (i < NN) {
        float d = g_wdeg[i];
        g_dinv[i] = (d > 0.f) ? rsqrtf(d) : 0.f;
    }
}

__global__ void scan_kernel() {
    __shared__ int ssum[1024];
    int tid = threadIdx.x;
    const int CH = (NN + 1023) / 1024;  // 49
    int start = tid * CH;
    int end = start + CH; if (end > NN) end = NN;
    int s = 0;
    for (int i = start; i < end && i < NN; i++) s += g_degcnt[i];
    ssum[tid] = s;
    __syncthreads();
    for (int off = 1; off < 1024; off <<= 1) {
        int v = (tid >= off) ? ssum[tid - off] : 0;
        __syncthreads();
        ssum[tid] += v;
        __syncthreads();
    }
    int run = ssum[tid] - s;  // exclusive prefix
    for (int i = start; i < end && i < NN; i++) {
        g_rowptr[i] = run;
        g_fill[i]   = run;
        run += g_degcnt[i];
    }
    if (tid == 1023) g_rowptr[NN] = ssum[1023];
}

__global__ void fill_kernel(const int* __restrict__ ei, const float* __restrict__ attr) {
    int e = blockIdx.x * blockDim.x + threadIdx.x;
    if (e < EE) {
        int r = ei[e];
        int c = ei[EE + e];
        float w = -attr[e] * g_dinv[r] * g_dinv[c];
        int pos = atomicAdd(&g_fill[r], 1);
        g_edges[pos] = make_int2(c, __float_as_int(w));
    }
}

// ---------------- sparse propagation: warp per row, gather formulation ----------------
// MODE 0: out = S*in        MODE 1: out = 2*S*in - sub
template <int MODE>
__global__ void prop_kernel(const float* __restrict__ in, float* __restrict__ out,
                            const float* __restrict__ sub) {
    int row = blockIdx.x * (blockDim.x >> 5) + (threadIdx.x >> 5);
    if (row >= NN) return;
    int lane = threadIdx.x & 31;
    int s = g_rowptr[row], e = g_rowptr[row + 1];
    const float2* in2 = (const float2*)in;
    float ax = 0.f, ay = 0.f;
    for (int j = s; j < e; j++) {
        int2 ed = g_edges[j];
        int c = ed.x;
        float wt = __int_as_float(ed.y);
        float2 v = in2[c * 32 + lane];
        ax = fmaf(wt, v.x, ax);
        ay = fmaf(wt, v.y, ay);
    }
    float2 o;
    if (MODE == 0) {
        o.x = ax; o.y = ay;
    } else {
        float2 sv = ((const float2*)sub)[row * 32 + lane];
        o.x = 2.f * ax - sv.x;
        o.y = 2.f * ay - sv.y;
    }
    ((float2*)out)[row * 32 + lane] = o;
}

// ---------------- fused 3-matrix GEMM: out = relu?(x0@W[0] + x1@W[1] + x2@W[2] + b) ----------------
// block: 64 rows x 64 cols, 256 threads, thread tile 4 rows x 4 cols
template <bool RELU>
__global__ __launch_bounds__(256, 2) void gemm3_kernel(
    const float* __restrict__ x0, const float* __restrict__ x1, const float* __restrict__ x2,
    const float* __restrict__ W, const float* __restrict__ b, float* __restrict__ out) {
    extern __shared__ float smem[];
    float* sW = smem;             // 3*64*64 floats
    float* sX = smem + 3 * 4096;  // 3*64*64 floats
    int tid = threadIdx.x;
    int row0 = blockIdx.x * 64;

    // stage W (48 KB)
    {
        float4* d = (float4*)sW;
        const float4* g = (const float4*)W;
        #pragma unroll
        for (int i = tid; i < 3 * 1024; i += 256) d[i] = g[i];
    }
    // stage X rows (3 x 64 x 64)
    {
        const float* xs0 = x0; const float* xs1 = x1; const float* xs2 = x2;
        for (int m = 0; m < 3; m++) {
            const float* src = (m == 0) ? xs0 : (m == 1) ? xs1 : xs2;
            float4* d = (float4*)(sX + m * 4096);
            const float4* g = (const float4*)src;
            for (int i = tid; i < 1024; i += 256) {
                int r = i >> 4, c = i & 15;
                int row = row0 + r;
                d[i] = (row < NN) ? g[row * 16 + c] : make_float4(0.f, 0.f, 0.f, 0.f);
            }
        }
    }
    __syncthreads();

    int tc = tid & 15;   // 4 cols each -> 64 cols
    int tr = tid >> 4;   // 4 rows each -> 64 rows
    float4 acc[4];
    #pragma unroll
    for (int i = 0; i < 4; i++) acc[i] = make_float4(0.f, 0.f, 0.f, 0.f);

    const float4* w0 = (const float4*)(sW);
    const float4* w1 = (const float4*)(sW + 4096);
    const float4* w2 = (const float4*)(sW + 8192);
    const float* X0 = sX;
    const float* X1 = sX + 4096;
    const float* X2 = sX + 8192;

    #pragma unroll 8
    for (int k = 0; k < 64; k++) {
        float4 a = w0[k * 16 + tc];
        float4 bq = w1[k * 16 + tc];
        float4 cq = w2[k * 16 + tc];
        #pragma unroll
        for (int i = 0; i < 4; i++) {
            int r = tr * 4 + i;
            float p = X0[r * 64 + k];
            float q = X1[r * 64 + k];
            float t = X2[r * 64 + k];
            acc[i].x += p * a.x + q * bq.x + t * cq.x;
            acc[i].y += p * a.y + q * bq.y + t * cq.y;
            acc[i].z += p * a.z + q * bq.z + t * cq.z;
            acc[i].w += p * a.w + q * bq.w + t * cq.w;
        }
    }

    float4 bias = ((const float4*)b)[tc];
    #pragma unroll
    for (int i = 0; i < 4; i++) {
        int row = row0 + tr * 4 + i;
        if (row < NN) {
            float4 o;
            o.x = acc[i].x + bias.x;
            o.y = acc[i].y + bias.y;
            o.z = acc[i].z + bias.z;
            o.w = acc[i].w + bias.w;
            if (RELU) {
                o.x = fmaxf(o.x, 0.f); o.y = fmaxf(o.y, 0.f);
                o.z = fmaxf(o.z, 0.f); o.w = fmaxf(o.w, 0.f);
            }
            ((float4*)out)[row * 16 + tc] = o;
        }
    }
}

// ---------------- mean pool per graph (batch is sorted) ----------------
__device__ __forceinline__ int lower_bound_batch(const int* b, int val) {
    int lo = 0, hi = NN;
    while (lo < hi) {
        int mid = (lo + hi) >> 1;
        if (b[mid] < val) lo = mid + 1; else hi = mid;
    }
    return lo;
}

__global__ void pool_kernel(const float* __restrict__ h, const int* __restrict__ batch) {
    int g = blockIdx.x;
    __shared__ int s_lo, s_hi;
    if (threadIdx.x == 0) {
        s_lo = lower_bound_batch(batch, g);
        s_hi = lower_bound_batch(batch, g + 1);
    }
    __syncthreads();
    int lo = s_lo, hi = s_hi;
    int f = threadIdx.x & 63;
    int part = threadIdx.x >> 6;  // 0..3
    float acc = 0.f;
    for (int i = lo + part; i < hi; i += 4) acc += h[i * 64 + f];
    __shared__ float sh[4][64];
    sh[part][f] = acc;
    __syncthreads();
    if (part == 0) {
        float s = sh[0][f] + sh[1][f] + sh[2][f] + sh[3][f];
        float cnt = (float)(hi - lo);
        g_pool[g * 64 + f] = s / fmaxf(cnt, 1.f);
    }
}

// ---------------- final MLP: [64,64]@[64,32]+relu -> @[32,10] ----------------
__global__ void mlp_kernel(const float* __restrict__ Wl1, const float* __restrict__ bl1,
                           const float* __restrict__ Wl2, const float* __restrict__ bl2,
                           float* __restrict__ out) {
    __shared__ float sp[GG * 64];
    __shared__ float sh1[GG * 32];
    int tid = threadIdx.x;
    for (int i = tid; i < GG * 64; i += 256) sp[i] = g_pool[i];
    __syncthreads();
    for (int i = tid; i < GG * 32; i += 256) {
        int g = i >> 5, c = i & 31;
        float s = bl1[c];
        #pragma unroll 8
        for (int k = 0; k < 64; k++) s += sp[g * 64 + k] * Wl1[k * 32 + c];
        sh1[i] = fmaxf(s, 0.f);
    }
    __syncthreads();
    for (int i = tid; i < GG * CC; i += 256) {
        int g = i / CC, c = i % CC;
        float s = bl2[c];
        #pragma unroll
        for (int k = 0; k < 32; k++) s += sh1[g * 32 + k] * Wl2[k * CC + c];
        out[i] = s;
    }
}

// ---------------- launcher ----------------
extern "C" void kernel_launch(void* const* d_in, const int* in_sizes, int n_in,
                              void* d_out, int out_size) {
    const float* x    = (const float*)d_in[0];
    const int*   ei   = (const int*)d_in[1];
    const float* attr = (const float*)d_in[2];
    const int*   bat  = (const int*)d_in[3];
    const float* W1 = (const float*)d_in[4];
    const float* b1 = (const float*)d_in[5];
    const float* W2 = (const float*)d_in[6];
    const float* b2 = (const float*)d_in[7];
    const float* W3 = (const float*)d_in[8];
    const float* b3 = (const float*)d_in[9];
    const float* Wl1 = (const float*)d_in[10];
    const float* bl1 = (const float*)d_in[11];
    const float* Wl2 = (const float*)d_in[12];
    const float* bl2 = (const float*)d_in[13];
    float* out = (float*)d_out;

    float *T1, *T2, *H0, *H1;
    cudaGetSymbolAddress((void**)&T1, g_T1);
    cudaGetSymbolAddress((void**)&T2, g_T2);
    cudaGetSymbolAddress((void**)&H0, g_H0);
    cudaGetSymbolAddress((void**)&H1, g_H1);

    const int SMEM = 3 * 4096 * 2 * (int)sizeof(float);  // 98304
    cudaFuncSetAttribute(gemm3_kernel<true>,  cudaFuncAttributeMaxDynamicSharedMemorySize, SMEM);
    cudaFuncSetAttribute(gemm3_kernel<false>, cudaFuncAttributeMaxDynamicSharedMemorySize, SMEM);

    const int NB_N = (NN + 255) / 256;
    const int NB_E = (EE + 255) / 256;
    const int NB_P = (NN + 7) / 8;        // warp per row, 8 warps/block
    const int NB_G = (NN + 63) / 64;      // gemm blocks

    zero_kernel<<<NB_N, 256>>>();
    deg_kernel<<<NB_E, 256>>>(ei, attr);
    dinv_kernel<<<NB_N, 256>>>();
    scan_kernel<<<1, 1024>>>();
    fill_kernel<<<NB_E, 256>>>(ei, attr);

    // Layer 1 (input = x)
    prop_kernel<0><<<NB_P, 256>>>(x, T1, nullptr);
    prop_kernel<1><<<NB_P, 256>>>(T1, T2, x);
    gemm3_kernel<true><<<NB_G, 256, SMEM>>>(x, T1, T2, W1, b1, H0);

    // Layer 2
    prop_kernel<0><<<NB_P, 256>>>(H0, T1, nullptr);
    prop_kernel<1><<<NB_P, 256>>>(T1, T2, H0);
    gemm3_kernel<true><<<NB_G, 256, SMEM>>>(H0, T1, T2, W2, b2, H1);

    // Layer 3 (no relu)
    prop_kernel<0><<<NB_P, 256>>>(H1, T1, nullptr);
    prop_kernel<1><<<NB_P, 256>>>(T1, T2, H1);
    gemm3_kernel<false><<<NB_G, 256, SMEM>>>(H1, T1, T2, W3, b3, H0);

    pool_kernel<<<GG, 256>>>(H0, bat);
    mlp_kernel<<<1, 256>>>(Wl1, bl1, Wl2, bl2, out);
}

// round 3
// speedup vs baseline: 1.2171x; 1.2171x over previous
#include <cuda_runtime.h>

#define NN 50000
#define EE 800000
#define F 64
#define GG 64
#define CC 10
#define NBLK 49   // ceil(NN/1024)

// ---------------- scratch (device globals; no allocation allowed) ----------------
__device__ __align__(16) float g_wdeg[NN];
__device__ __align__(16) float g_dinv[NN];
__device__ __align__(16) int   g_degcnt[NN];
__device__ __align__(16) int   g_rowptr[NN + 1];
__device__ __align__(16) int   g_fill[NN];
__device__ __align__(16) int   g_blksum[NBLK];
__device__ __align__(16) int   g_blkoff[NBLK];
__device__ __align__(16) int2  g_edges[EE];      // (col, bitcast(norm)) sorted by row
__device__ __align__(16) float g_T1[NN * F];
__device__ __align__(16) float g_T2[NN * F];
__device__ __align__(16) float g_H0[NN * F];
__device__ __align__(16) float g_H1[NN * F];
__device__ __align__(16) float g_pool[GG * F];

// ---------------- build: degree, dinv, CSR ----------------
__global__ void zero_kernel() {
    int i = blockIdx.x * blockDim.x + threadIdx.x;
    if (i < NN) { g_wdeg[i] = 0.f; g_degcnt[i] = 0; }
}

__global__ void deg_kernel(const int* __restrict__ ei, const float* __restrict__ attr) {
    int e = blockIdx.x * blockDim.x + threadIdx.x;
    if (e < EE) {
        int r = ei[e];
        atomicAdd(&g_wdeg[r], attr[e]);
        atomicAdd(&g_degcnt[r], 1);
    }
}

// Multi-block scan, stage 1: block-local exclusive scan of degcnt + per-block sums.
// Also fuses dinv computation (same dependency: deg_kernel).
__global__ void scan1_kernel() {
    int tid = threadIdx.x;
    int i = blockIdx.x * 1024 + tid;
    int v = (i < NN) ? g_degcnt[i] : 0;

    if (i < NN) {
        float d = g_wdeg[i];
        g_dinv[i] = (d > 0.f) ? rsqrtf(d) : 0.f;
    }

    int lane = tid & 31, wid = tid >> 5;
    // warp inclusive scan
    int x = v;
    #pragma unroll
    for (int o = 1; o < 32; o <<= 1) {
        int y = __shfl_up_sync(0xFFFFFFFFu, x, o);
        if (lane >= o) x += y;
    }
    __shared__ int ws[32];
    if (lane == 31) ws[wid] = x;
    __syncthreads();
    if (wid == 0) {
        int s = ws[lane];
        #pragma unroll
        for (int o = 1; o < 32; o <<= 1) {
            int y = __shfl_up_sync(0xFFFFFFFFu, s, o);
            if (lane >= o) s += y;
        }
        ws[lane] = s;  // inclusive scan of warp sums
    }
    __syncthreads();
    int excl = x - v + (wid > 0 ? ws[wid - 1] : 0);
    if (i < NN) g_rowptr[i] = excl;  // block-local exclusive; offset added in scan3
    if (tid == 1023) g_blksum[blockIdx.x] = ws[31];
}

// stage 2: exclusive scan of the 49 block sums (one warp, 2 elems/lane)
__global__ void scan2_kernel() {
    int t = threadIdx.x;  // blockDim = 32
    int i0 = 2 * t, i1 = 2 * t + 1;
    int v0 = (i0 < NBLK) ? g_blksum[i0] : 0;
    int v1 = (i1 < NBLK) ? g_blksum[i1] : 0;
    int p = v0 + v1;
    int x = p;
    #pragma unroll
    for (int o = 1; o < 32; o <<= 1) {
        int y = __shfl_up_sync(0xFFFFFFFFu, x, o);
        if (t >= o) x += y;
    }
    int excl = x - p;
    if (i0 < NBLK) g_blkoff[i0] = excl;
    if (i1 < NBLK) g_blkoff[i1] = excl + v0;
    if (t == 31) g_rowptr[NN] = x;  // total == EE
}

// stage 3: add block offsets, init fill cursors
__global__ void scan3_kernel() {
    int i = blockIdx.x * 1024 + threadIdx.x;
    if (i < NN) {
        int r = g_rowptr[i] + g_blkoff[blockIdx.x];
        g_rowptr[i] = r;
        g_fill[i]   = r;
    }
}

__global__ void fill_kernel(const int* __restrict__ ei, const float* __restrict__ attr) {
    int e = blockIdx.x * blockDim.x + threadIdx.x;
    if (e < EE) {
        int r = ei[e];
        int c = ei[EE + e];
        float w = -attr[e] * g_dinv[r] * g_dinv[c];
        int pos = atomicAdd(&g_fill[r], 1);
        g_edges[pos] = make_int2(c, __float_as_int(w));
    }
}

// ---------------- sparse propagation: warp per row, gather formulation ----------------
// MODE 0: out = S*in        MODE 1: out = 2*S*in - sub
template <int MODE>
__global__ void prop_kernel(const float* __restrict__ in, float* __restrict__ out,
                            const float* __restrict__ sub) {
    int row = blockIdx.x * (blockDim.x >> 5) + (threadIdx.x >> 5);
    if (row >= NN) return;
    int lane = threadIdx.x & 31;
    int s = g_rowptr[row], e = g_rowptr[row + 1];
    const float2* in2 = (const float2*)in;
    float ax = 0.f, ay = 0.f;
    for (int j = s; j < e; j++) {
        int2 ed = g_edges[j];
        int c = ed.x;
        float wt = __int_as_float(ed.y);
        float2 v = in2[c * 32 + lane];
        ax = fmaf(wt, v.x, ax);
        ay = fmaf(wt, v.y, ay);
    }
    float2 o;
    if (MODE == 0) {
        o.x = ax; o.y = ay;
    } else {
        float2 sv = ((const float2*)sub)[row * 32 + lane];
        o.x = 2.f * ax - sv.x;
        o.y = 2.f * ay - sv.y;
    }
    ((float2*)out)[row * 32 + lane] = o;
}

// ---------------- fused 3-matrix GEMM: out = relu?(x0@W[0] + x1@W[1] + x2@W[2] + b) ----------------
// block: 64 rows x 64 cols, 256 threads, thread tile 4 rows x 4 cols
template <bool RELU>
__global__ __launch_bounds__(256, 2) void gemm3_kernel(
    const float* __restrict__ x0, const float* __restrict__ x1, const float* __restrict__ x2,
    const float* __restrict__ W, const float* __restrict__ b, float* __restrict__ out) {
    extern __shared__ float smem[];
    float* sW = smem;             // 3*64*64 floats
    float* sX = smem + 3 * 4096;  // 3*64*64 floats
    int tid = threadIdx.x;
    int row0 = blockIdx.x * 64;

    // stage W (48 KB)
    {
        float4* d = (float4*)sW;
        const float4* g = (const float4*)W;
        #pragma unroll
        for (int i = tid; i < 3 * 1024; i += 256) d[i] = g[i];
    }
    // stage X rows (3 x 64 x 64)
    {
        for (int m = 0; m < 3; m++) {
            const float* src = (m == 0) ? x0 : (m == 1) ? x1 : x2;
            float4* d = (float4*)(sX + m * 4096);
            const float4* g = (const float4*)src;
            for (int i = tid; i < 1024; i += 256) {
                int r = i >> 4, c = i & 15;
                int row = row0 + r;
                d[i] = (row < NN) ? g[row * 16 + c] : make_float4(0.f, 0.f, 0.f, 0.f);
            }
        }
    }
    __syncthreads();

    int tc = tid & 15;   // 4 cols each -> 64 cols
    int tr = tid >> 4;   // 4 rows each -> 64 rows
    float4 acc[4];
    #pragma unroll
    for (int i = 0; i < 4; i++) acc[i] = make_float4(0.f, 0.f, 0.f, 0.f);

    const float4* w0 = (const float4*)(sW);
    const float4* w1 = (const float4*)(sW + 4096);
    const float4* w2 = (const float4*)(sW + 8192);
    const float* X0 = sX;
    const float* X1 = sX + 4096;
    const float* X2 = sX + 8192;

    #pragma unroll 8
    for (int k = 0; k < 64; k++) {
        float4 a = w0[k * 16 + tc];
        float4 bq = w1[k * 16 + tc];
        float4 cq = w2[k * 16 + tc];
        #pragma unroll
        for (int i = 0; i < 4; i++) {
            int r = tr * 4 + i;
            float p = X0[r * 64 + k];
            float q = X1[r * 64 + k];
            float t = X2[r * 64 + k];
            acc[i].x += p * a.x + q * bq.x + t * cq.x;
            acc[i].y += p * a.y + q * bq.y + t * cq.y;
            acc[i].z += p * a.z + q * bq.z + t * cq.z;
            acc[i].w += p * a.w + q * bq.w + t * cq.w;
        }
    }

    float4 bias = ((const float4*)b)[tc];
    #pragma unroll
    for (int i = 0; i < 4; i++) {
        int row = row0 + tr * 4 + i;
        if (row < NN) {
            float4 o;
            o.x = acc[i].x + bias.x;
            o.y = acc[i].y + bias.y;
            o.z = acc[i].z + bias.z;
            o.w = acc[i].w + bias.w;
            if (RELU) {
                o.x = fmaxf(o.x, 0.f); o.y = fmaxf(o.y, 0.f);
                o.z = fmaxf(o.z, 0.f); o.w = fmaxf(o.w, 0.f);
            }
            ((float4*)out)[row * 16 + tc] = o;
        }
    }
}

// ---------------- mean pool per graph (batch is sorted) ----------------
__device__ __forceinline__ int lower_bound_batch(const int* b, int val) {
    int lo = 0, hi = NN;
    while (lo < hi) {
        int mid = (lo + hi) >> 1;
        if (b[mid] < val) lo = mid + 1; else hi = mid;
    }
    return lo;
}

__global__ void pool_kernel(const float* __restrict__ h, const int* __restrict__ batch) {
    int g = blockIdx.x;
    __shared__ int s_lo, s_hi;
    if (threadIdx.x == 0) {
        s_lo = lower_bound_batch(batch, g);
        s_hi = lower_bound_batch(batch, g + 1);
    }
    __syncthreads();
    int lo = s_lo, hi = s_hi;
    int f = threadIdx.x & 63;
    int part = threadIdx.x >> 6;  // 0..3
    float acc = 0.f;
    for (int i = lo + part; i < hi; i += 4) acc += h[i * 64 + f];
    __shared__ float sh[4][64];
    sh[part][f] = acc;
    __syncthreads();
    if (part == 0) {
        float s = sh[0][f] + sh[1][f] + sh[2][f] + sh[3][f];
        float cnt = (float)(hi - lo);
        g_pool[g * 64 + f] = s / fmaxf(cnt, 1.f);
    }
}

// ---------------- final MLP: [64,64]@[64,32]+relu -> @[32,10] ----------------
__global__ void mlp_kernel(const float* __restrict__ Wl1, const float* __restrict__ bl1,
                           const float* __restrict__ Wl2, const float* __restrict__ bl2,
                           float* __restrict__ out) {
    __shared__ float sp[GG * 64];
    __shared__ float sh1[GG * 32];
    int tid = threadIdx.x;
    for (int i = tid; i < GG * 64; i += 256) sp[i] = g_pool[i];
    __syncthreads();
    for (int i = tid; i < GG * 32; i += 256) {
        int g = i >> 5, c = i & 31;
        float s = bl1[c];
        #pragma unroll 8
        for (int k = 0; k < 64; k++) s += sp[g * 64 + k] * Wl1[k * 32 + c];
        sh1[i] = fmaxf(s, 0.f);
    }
    __syncthreads();
    for (int i = tid; i < GG * CC; i += 256) {
        int g = i / CC, c = i % CC;
        float s = bl2[c];
        #pragma unroll
        for (int k = 0; k < 32; k++) s += sh1[g * 32 + k] * Wl2[k * CC + c];
        out[i] = s;
    }
}

// ---------------- launcher ----------------
extern "C" void kernel_launch(void* const* d_in, const int* in_sizes, int n_in,
                              void* d_out, int out_size) {
    const float* x    = (const float*)d_in[0];
    const int*   ei   = (const int*)d_in[1];
    const float* attr = (const float*)d_in[2];
    const int*   bat  = (const int*)d_in[3];
    const float* W1 = (const float*)d_in[4];
    const float* b1 = (const float*)d_in[5];
    const float* W2 = (const float*)d_in[6];
    const float* b2 = (const float*)d_in[7];
    const float* W3 = (const float*)d_in[8];
    const float* b3 = (const float*)d_in[9];
    const float* Wl1 = (const float*)d_in[10];
    const float* bl1 = (const float*)d_in[11];
    const float* Wl2 = (const float*)d_in[12];
    const float* bl2 = (const float*)d_in[13];
    float* out = (float*)d_out;

    float *T1, *T2, *H0, *H1;
    cudaGetSymbolAddress((void**)&T1, g_T1);
    cudaGetSymbolAddress((void**)&T2, g_T2);
    cudaGetSymbolAddress((void**)&H0, g_H0);
    cudaGetSymbolAddress((void**)&H1, g_H1);

    const int SMEM = 3 * 4096 * 2 * (int)sizeof(float);  // 98304
    cudaFuncSetAttribute(gemm3_kernel<true>,  cudaFuncAttributeMaxDynamicSharedMemorySize, SMEM);
    cudaFuncSetAttribute(gemm3_kernel<false>, cudaFuncAttributeMaxDynamicSharedMemorySize, SMEM);

    const int NB_N = (NN + 255) / 256;
    const int NB_E = (EE + 255) / 256;
    const int NB_P = (NN + 7) / 8;        // warp per row, 8 warps/block
    const int NB_G = (NN + 63) / 64;      // gemm blocks

    zero_kernel<<<NB_N, 256>>>();
    deg_kernel<<<NB_E, 256>>>(ei, attr);
    scan1_kernel<<<NBLK, 1024>>>();       // block scans + dinv (fused)
    scan2_kernel<<<1, 32>>>();            // scan of block sums
    scan3_kernel<<<NBLK, 1024>>>();       // add offsets
    fill_kernel<<<NB_E, 256>>>(ei, attr);

    // Layer 1 (input = x)
    prop_kernel<0><<<NB_P, 256>>>(x, T1, nullptr);
    prop_kernel<1><<<NB_P, 256>>>(T1, T2, x);
    gemm3_kernel<true><<<NB_G, 256, SMEM>>>(x, T1, T2, W1, b1, H0);

    // Layer 2
    prop_kernel<0><<<NB_P, 256>>>(H0, T1, nullptr);
    prop_kernel<1><<<NB_P, 256>>>(T1, T2, H0);
    gemm3_kernel<true><<<NB_G, 256, SMEM>>>(H0, T1, T2, W2, b2, H1);

    // Layer 3 (no relu)
    prop_kernel<0><<<NB_P, 256>>>(H1, T1, nullptr);
    prop_kernel<1><<<NB_P, 256>>>(T1, T2, H1);
    gemm3_kernel<false><<<NB_G, 256, SMEM>>>(H1, T1, T2, W3, b3, H0);

    pool_kernel<<<GG, 256>>>(H0, bat);
    mlp_kernel<<<1, 256>>>(Wl1, bl1, Wl2, bl2, out);
}

// round 4
// speedup vs baseline: 1.2777x; 1.0498x over previous
#include <cuda_runtime.h>

#define NN 50000
#define EE 800000
#define F 64
#define GG 64
#define CC 10
#define NBLK 49   // ceil(NN/1024)

// ---------------- scratch (device globals; no allocation allowed) ----------------
__device__ __align__(16) float g_wdeg[NN];
__device__ __align__(16) float g_dinv[NN];
__device__ __align__(16) int   g_degcnt[NN];
__device__ __align__(16) int   g_rowptr[NN + 1];
__device__ __align__(16) int   g_fill[NN];
__device__ __align__(16) int   g_blksum[NBLK];
__device__ __align__(16) int   g_blkoff[NBLK];
__device__ __align__(16) int2  g_edges[EE];      // (col, bitcast(norm)) sorted by row
__device__ __align__(16) float g_T1[NN * F];
__device__ __align__(16) float g_T2[NN * F];
__device__ __align__(16) float g_H0[NN * F];
__device__ __align__(16) float g_H1[NN * F];
__device__ __align__(16) float g_pool[GG * F];

// ---------------- packed f32x2 helpers ----------------
__device__ __forceinline__ void fma2(unsigned long long& d, unsigned long long a, unsigned long long b) {
    asm("fma.rn.f32x2 %0, %1, %2, %0;" : "+l"(d) : "l"(a), "l"(b));
}
__device__ __forceinline__ unsigned long long pk2(float lo, float hi) {
    unsigned long long r;
    asm("mov.b64 %0, {%1, %2};" : "=l"(r) : "f"(lo), "f"(hi));
    return r;
}
__device__ __forceinline__ float2 unpk2(unsigned long long v) {
    float2 r;
    asm("mov.b64 {%0, %1}, %2;" : "=f"(r.x), "=f"(r.y) : "l"(v));
    return r;
}

// ---------------- build: degree, dinv, CSR ----------------
__global__ void zero_kernel() {
    int i = blockIdx.x * blockDim.x + threadIdx.x;
    if (i < NN) { g_wdeg[i] = 0.f; g_degcnt[i] = 0; }
}

__global__ void deg_kernel(const int* __restrict__ ei, const float* __restrict__ attr) {
    int e = blockIdx.x * blockDim.x + threadIdx.x;
    if (e < EE) {
        int r = ei[e];
        atomicAdd(&g_wdeg[r], attr[e]);
        atomicAdd(&g_degcnt[r], 1);
    }
}

// Multi-block scan, stage 1: block-local exclusive scan of degcnt + per-block sums + dinv.
__global__ void scan1_kernel() {
    int tid = threadIdx.x;
    int i = blockIdx.x * 1024 + tid;
    int v = (i < NN) ? g_degcnt[i] : 0;

    if (i < NN) {
        float d = g_wdeg[i];
        g_dinv[i] = (d > 0.f) ? rsqrtf(d) : 0.f;
    }

    int lane = tid & 31, wid = tid >> 5;
    int x = v;
    #pragma unroll
    for (int o = 1; o < 32; o <<= 1) {
        int y = __shfl_up_sync(0xFFFFFFFFu, x, o);
        if (lane >= o) x += y;
    }
    __shared__ int ws[32];
    if (lane == 31) ws[wid] = x;
    __syncthreads();
    if (wid == 0) {
        int s = ws[lane];
        #pragma unroll
        for (int o = 1; o < 32; o <<= 1) {
            int y = __shfl_up_sync(0xFFFFFFFFu, s, o);
            if (lane >= o) s += y;
        }
        ws[lane] = s;
    }
    __syncthreads();
    int excl = x - v + (wid > 0 ? ws[wid - 1] : 0);
    if (i < NN) g_rowptr[i] = excl;
    if (tid == 1023) g_blksum[blockIdx.x] = ws[31];
}

__global__ void scan2_kernel() {
    int t = threadIdx.x;  // blockDim = 32
    int i0 = 2 * t, i1 = 2 * t + 1;
    int v0 = (i0 < NBLK) ? g_blksum[i0] : 0;
    int v1 = (i1 < NBLK) ? g_blksum[i1] : 0;
    int p = v0 + v1;
    int x = p;
    #pragma unroll
    for (int o = 1; o < 32; o <<= 1) {
        int y = __shfl_up_sync(0xFFFFFFFFu, x, o);
        if (t >= o) x += y;
    }
    int excl = x - p;
    if (i0 < NBLK) g_blkoff[i0] = excl;
    if (i1 < NBLK) g_blkoff[i1] = excl + v0;
    if (t == 31) g_rowptr[NN] = x;
}

__global__ void scan3_kernel() {
    int i = blockIdx.x * 1024 + threadIdx.x;
    if (i < NN) {
        int r = g_rowptr[i] + g_blkoff[blockIdx.x];
        g_rowptr[i] = r;
        g_fill[i]   = r;
    }
}

__global__ void fill_kernel(const int* __restrict__ ei, const float* __restrict__ attr) {
    int e = blockIdx.x * blockDim.x + threadIdx.x;
    if (e < EE) {
        int r = ei[e];
        int c = ei[EE + e];
        float w = -attr[e] * g_dinv[r] * g_dinv[c];
        int pos = atomicAdd(&g_fill[r], 1);
        g_edges[pos] = make_int2(c, __float_as_int(w));
    }
}

// ---------------- sparse propagation: warp per row, 4x unrolled gather ----------------
// MODE 0: out = S*in        MODE 1: out = 2*S*in - sub
template <int MODE>
__global__ void prop_kernel(const float* __restrict__ in, float* __restrict__ out,
                            const float* __restrict__ sub) {
    int row = blockIdx.x * (blockDim.x >> 5) + (threadIdx.x >> 5);
    if (row >= NN) return;
    int lane = threadIdx.x & 31;
    int s = g_rowptr[row], e = g_rowptr[row + 1];
    const float2* in2 = (const float2*)in;

    float ax = 0.f, ay = 0.f, bx = 0.f, by = 0.f;
    float cx = 0.f, cy = 0.f, dx = 0.f, dy = 0.f;
    int j = s;
    for (; j + 4 <= e; j += 4) {
        int2 e0 = g_edges[j];
        int2 e1 = g_edges[j + 1];
        int2 e2 = g_edges[j + 2];
        int2 e3 = g_edges[j + 3];
        float2 v0 = in2[e0.x * 32 + lane];
        float2 v1 = in2[e1.x * 32 + lane];
        float2 v2 = in2[e2.x * 32 + lane];
        float2 v3 = in2[e3.x * 32 + lane];
        ax = fmaf(__int_as_float(e0.y), v0.x, ax);
        ay = fmaf(__int_as_float(e0.y), v0.y, ay);
        bx = fmaf(__int_as_float(e1.y), v1.x, bx);
        by = fmaf(__int_as_float(e1.y), v1.y, by);
        cx = fmaf(__int_as_float(e2.y), v2.x, cx);
        cy = fmaf(__int_as_float(e2.y), v2.y, cy);
        dx = fmaf(__int_as_float(e3.y), v3.x, dx);
        dy = fmaf(__int_as_float(e3.y), v3.y, dy);
    }
    for (; j < e; j++) {
        int2 ed = g_edges[j];
        float2 v = in2[ed.x * 32 + lane];
        ax = fmaf(__int_as_float(ed.y), v.x, ax);
        ay = fmaf(__int_as_float(ed.y), v.y, ay);
    }
    float sx = (ax + bx) + (cx + dx);
    float sy = (ay + by) + (cy + dy);

    float2 o;
    if (MODE == 0) {
        o.x = sx; o.y = sy;
    } else {
        float2 sv = ((const float2*)sub)[row * 32 + lane];
        o.x = 2.f * sx - sv.x;
        o.y = 2.f * sy - sv.y;
    }
    ((float2*)out)[row * 32 + lane] = o;
}

// ---------------- fused 3-matrix GEMM with packed f32x2 FMA ----------------
// out = relu?(x0@W[0] + x1@W[1] + x2@W[2] + b)
// block: 64 rows x 64 cols, 256 threads, thread tile 4 rows x 4 cols
template <bool RELU>
__global__ __launch_bounds__(256, 2) void gemm3_kernel(
    const float* __restrict__ x0, const float* __restrict__ x1, const float* __restrict__ x2,
    const float* __restrict__ W, const float* __restrict__ b, float* __restrict__ out) {
    extern __shared__ float smem[];
    float* sW = smem;             // 3*64*64 floats
    float* sX = smem + 3 * 4096;  // 3*64*64 floats
    int tid = threadIdx.x;
    int row0 = blockIdx.x * 64;

    // stage W (48 KB)
    {
        float4* d = (float4*)sW;
        const float4* g = (const float4*)W;
        #pragma unroll
        for (int i = tid; i < 3 * 1024; i += 256) d[i] = g[i];
    }
    // stage X rows (3 x 64 x 64)
    {
        for (int m = 0; m < 3; m++) {
            const float* src = (m == 0) ? x0 : (m == 1) ? x1 : x2;
            float4* d = (float4*)(sX + m * 4096);
            const float4* g = (const float4*)src;
            for (int i = tid; i < 1024; i += 256) {
                int r = i >> 4, c = i & 15;
                int row = row0 + r;
                d[i] = (row < NN) ? g[row * 16 + c] : make_float4(0.f, 0.f, 0.f, 0.f);
            }
        }
    }
    __syncthreads();

    int tc = tid & 15;   // 4 cols each -> 64 cols
    int tr = tid >> 4;   // 4 rows each -> 64 rows

    unsigned long long accA[4], accB[4];  // (col x,y) and (col z,w) per row
    #pragma unroll
    for (int i = 0; i < 4; i++) { accA[i] = 0ull; accB[i] = 0ull; }

    const float4* w0 = (const float4*)(sW);
    const float4* w1 = (const float4*)(sW + 4096);
    const float4* w2 = (const float4*)(sW + 8192);
    const float* X0 = sX;
    const float* X1 = sX + 4096;
    const float* X2 = sX + 8192;

    #pragma unroll 4
    for (int k = 0; k < 64; k += 4) {
        float4 a0[4], a1[4], a2[4];
        #pragma unroll
        for (int i = 0; i < 4; i++) {
            int r = tr * 4 + i;
            a0[i] = *(const float4*)(X0 + r * 64 + k);
            a1[i] = *(const float4*)(X1 + r * 64 + k);
            a2[i] = *(const float4*)(X2 + r * 64 + k);
        }
        #pragma unroll
        for (int j = 0; j < 4; j++) {
            float4 w0v = w0[(k + j) * 16 + tc];
            float4 w1v = w1[(k + j) * 16 + tc];
            float4 w2v = w2[(k + j) * 16 + tc];
            unsigned long long w0xy = pk2(w0v.x, w0v.y), w0zw = pk2(w0v.z, w0v.w);
            unsigned long long w1xy = pk2(w1v.x, w1v.y), w1zw = pk2(w1v.z, w1v.w);
            unsigned long long w2xy = pk2(w2v.x, w2v.y), w2zw = pk2(w2v.z, w2v.w);
            #pragma unroll
            for (int i = 0; i < 4; i++) {
                float p = ((const float*)&a0[i])[j];
                float q = ((const float*)&a1[i])[j];
                float t = ((const float*)&a2[i])[j];
                unsigned long long pp = pk2(p, p);
                unsigned long long qq = pk2(q, q);
                unsigned long long tt = pk2(t, t);
                fma2(accA[i], w0xy, pp);
                fma2(accB[i], w0zw, pp);
                fma2(accA[i], w1xy, qq);
                fma2(accB[i], w1zw, qq);
                fma2(accA[i], w2xy, tt);
                fma2(accB[i], w2zw, tt);
            }
        }
    }

    float4 bias = ((const float4*)b)[tc];
    #pragma unroll
    for (int i = 0; i < 4; i++) {
        int row = row0 + tr * 4 + i;
        if (row < NN) {
            float2 lo = unpk2(accA[i]);
            float2 hi = unpk2(accB[i]);
            float4 o;
            o.x = lo.x + bias.x;
            o.y = lo.y + bias.y;
            o.z = hi.x + bias.z;
            o.w = hi.y + bias.w;
            if (RELU) {
                o.x = fmaxf(o.x, 0.f); o.y = fmaxf(o.y, 0.f);
                o.z = fmaxf(o.z, 0.f); o.w = fmaxf(o.w, 0.f);
            }
            ((float4*)out)[row * 16 + tc] = o;
        }
    }
}

// ---------------- mean pool per graph (batch is sorted) ----------------
__device__ __forceinline__ int lower_bound_batch(const int* b, int val) {
    int lo = 0, hi = NN;
    while (lo < hi) {
        int mid = (lo + hi) >> 1;
        if (b[mid] < val) lo = mid + 1; else hi = mid;
    }
    return lo;
}

__global__ void pool_kernel(const float* __restrict__ h, const int* __restrict__ batch) {
    int g = blockIdx.x;
    __shared__ int s_lo, s_hi;
    if (threadIdx.x == 0) {
        s_lo = lower_bound_batch(batch, g);
        s_hi = lower_bound_batch(batch, g + 1);
    }
    __syncthreads();
    int lo = s_lo, hi = s_hi;
    int f = threadIdx.x & 63;
    int part = threadIdx.x >> 6;  // 0..3
    float acc = 0.f;
    for (int i = lo + part; i < hi; i += 4) acc += h[i * 64 + f];
    __shared__ float sh[4][64];
    sh[part][f] = acc;
    __syncthreads();
    if (part == 0) {
        float s = sh[0][f] + sh[1][f] + sh[2][f] + sh[3][f];
        float cnt = (float)(hi - lo);
        g_pool[g * 64 + f] = s / fmaxf(cnt, 1.f);
    }
}

// ---------------- final MLP: [64,64]@[64,32]+relu -> @[32,10] ----------------
__global__ void mlp_kernel(const float* __restrict__ Wl1, const float* __restrict__ bl1,
                           const float* __restrict__ Wl2, const float* __restrict__ bl2,
                           float* __restrict__ out) {
    __shared__ float sp[GG * 64];
    __shared__ float sh1[GG * 32];
    int tid = threadIdx.x;
    for (int i = tid; i < GG * 64; i += 256) sp[i] = g_pool[i];
    __syncthreads();
    for (int i = tid; i < GG * 32; i += 256) {
        int g = i >> 5, c = i & 31;
        float s = bl1[c];
        #pragma unroll 8
        for (int k = 0; k < 64; k++) s += sp[g * 64 + k] * Wl1[k * 32 + c];
        sh1[i] = fmaxf(s, 0.f);
    }
    __syncthreads();
    for (int i = tid; i < GG * CC; i += 256) {
        int g = i / CC, c = i % CC;
        float s = bl2[c];
        #pragma unroll
        for (int k = 0; k < 32; k++) s += sh1[g * 32 + k] * Wl2[k * CC + c];
        out[i] = s;
    }
}

// ---------------- launcher ----------------
extern "C" void kernel_launch(void* const* d_in, const int* in_sizes, int n_in,
                              void* d_out, int out_size) {
    const float* x    = (const float*)d_in[0];
    const int*   ei   = (const int*)d_in[1];
    const float* attr = (const float*)d_in[2];
    const int*   bat  = (const int*)d_in[3];
    const float* W1 = (const float*)d_in[4];
    const float* b1 = (const float*)d_in[5];
    const float* W2 = (const float*)d_in[6];
    const float* b2 = (const float*)d_in[7];
    const float* W3 = (const float*)d_in[8];
    const float* b3 = (const float*)d_in[9];
    const float* Wl1 = (const float*)d_in[10];
    const float* bl1 = (const float*)d_in[11];
    const float* Wl2 = (const float*)d_in[12];
    const float* bl2 = (const float*)d_in[13];
    float* out = (float*)d_out;

    float *T1, *T2, *H0, *H1;
    cudaGetSymbolAddress((void**)&T1, g_T1);
    cudaGetSymbolAddress((void**)&T2, g_T2);
    cudaGetSymbolAddress((void**)&H0, g_H0);
    cudaGetSymbolAddress((void**)&H1, g_H1);

    const int SMEM = 3 * 4096 * 2 * (int)sizeof(float);  // 98304
    cudaFuncSetAttribute(gemm3_kernel<true>,  cudaFuncAttributeMaxDynamicSharedMemorySize, SMEM);
    cudaFuncSetAttribute(gemm3_kernel<false>, cudaFuncAttributeMaxDynamicSharedMemorySize, SMEM);

    const int NB_N = (NN + 255) / 256;
    const int NB_E = (EE + 255) / 256;
    const int NB_P = (NN + 7) / 8;        // warp per row, 8 warps/block
    const int NB_G = (NN + 63) / 64;      // gemm blocks

    zero_kernel<<<NB_N, 256>>>();
    deg_kernel<<<NB_E, 256>>>(ei, attr);
    scan1_kernel<<<NBLK, 1024>>>();
    scan2_kernel<<<1, 32>>>();
    scan3_kernel<<<NBLK, 1024>>>();
    fill_kernel<<<NB_E, 256>>>(ei, attr);

    // Layer 1 (input = x)
    prop_kernel<0><<<NB_P, 256>>>(x, T1, nullptr);
    prop_kernel<1><<<NB_P, 256>>>(T1, T2, x);
    gemm3_kernel<true><<<NB_G, 256, SMEM>>>(x, T1, T2, W1, b1, H0);

    // Layer 2
    prop_kernel<0><<<NB_P, 256>>>(H0, T1, nullptr);
    prop_kernel<1><<<NB_P, 256>>>(T1, T2, H0);
    gemm3_kernel<true><<<NB_G, 256, SMEM>>>(H0, T1, T2, W2, b2, H1);

    // Layer 3 (no relu)
    prop_kernel<0><<<NB_P, 256>>>(H1, T1, nullptr);
    prop_kernel<1><<<NB_P, 256>>>(T1, T2, H1);
    gemm3_kernel<false><<<NB_G, 256, SMEM>>>(H1, T1, T2, W3, b3, H0);

    pool_kernel<<<GG, 256>>>(H0, bat);
    mlp_kernel<<<1, 256>>>(Wl1, bl1, Wl2, bl2, out);
}